// round 14
// baseline (speedup 1.0000x reference)
#include <cuda_runtime.h>
#include <cstdint>

#define BB 2
#define LL 2048
#define DD 1024
#define HH 16
#define DH 64

// scratch for attention output (merged heads), [B, L, D] fp32 = 16 MB
__device__ float g_attn[BB * LL * DD];

// ---------------------------------------------------------------------------
// tf32 helpers
// ---------------------------------------------------------------------------
__device__ __forceinline__ uint32_t f2tf32(float x) {
    uint32_t r;
    asm("cvt.rna.tf32.f32 %0, %1;" : "=r"(r) : "f"(x));
    return r;
}
__device__ __forceinline__ float tf(float x) { return __uint_as_float(f2tf32(x)); }

__device__ __forceinline__ void mma_tf32(float c[4],
                                         uint32_t a0, uint32_t a1, uint32_t a2, uint32_t a3,
                                         uint32_t b0, uint32_t b1)
{
    asm volatile(
        "mma.sync.aligned.m16n8k8.row.col.f32.tf32.tf32.f32 "
        "{%0,%1,%2,%3}, {%4,%5,%6,%7}, {%8,%9}, {%0,%1,%2,%3};\n"
        : "+f"(c[0]), "+f"(c[1]), "+f"(c[2]), "+f"(c[3])
        : "r"(a0), "r"(a1), "r"(a2), "r"(a3), "r"(b0), "r"(b1));
}

// ---------------------------------------------------------------------------
// Flash attention with tf32 tensor-core mma.
// Block: 128 threads = 4 warps; each warp owns 16 query rows (BM=64).
// BN=64 keys per iteration. Q fragments live in registers for the whole loop.
// Smem: KP (K tile as Ks[key][d], reused as Ps[qrow][key]) pad 68,
//       Vs[key][d] pad 72.
// ---------------------------------------------------------------------------
__global__ __launch_bounds__(128) void attn_tc(
    const float* __restrict__ Q,
    const float* __restrict__ K,
    const float* __restrict__ V)
{
    __shared__ float KP[64][68];   // 17408 B
    __shared__ float Vs[64][72];   // 18432 B

    const int tid  = threadIdx.x;
    const int warp = tid >> 5;
    const int lane = tid & 31;
    const int g    = lane >> 2;    // 0..7
    const int tig  = lane & 3;     // 0..3

    const int qt = gridDim.x - 1 - (int)blockIdx.x;   // heavy tiles first
    const int h  = blockIdx.y;
    const int b  = blockIdx.z;
    const int q0 = qt * 64;
    const int m0 = warp * 16;

    const size_t base = (size_t)b * LL * DD + (size_t)h * DH;

    // ---- Q fragments for all 8 k8-chunks of DH=64, pre-scaled by 1/8, tf32 ----
    uint32_t qa[8][4];
    {
        const float* qr0 = Q + base + (size_t)(q0 + m0 + g) * DD;
        const float* qr1 = qr0 + (size_t)8 * DD;
        #pragma unroll
        for (int s = 0; s < 8; ++s) {
            qa[s][0] = f2tf32(qr0[8 * s + tig] * 0.125f);
            qa[s][1] = f2tf32(qr1[8 * s + tig] * 0.125f);
            qa[s][2] = f2tf32(qr0[8 * s + tig + 4] * 0.125f);
            qa[s][3] = f2tf32(qr1[8 * s + tig + 4] * 0.125f);
        }
    }

    float o[8][4];
    #pragma unroll
    for (int j = 0; j < 8; ++j)
        #pragma unroll
        for (int r = 0; r < 4; ++r) o[j][r] = 0.0f;

    float m_lo = -1e30f, m_hi = -1e30f;
    float l_lo = 0.0f,   l_hi = 0.0f;

    for (int kv = 0; kv <= qt; ++kv) {
        const int k0 = kv * 64;

        __syncthreads();   // previous iter done reading KP(Ps) and Vs

        // ---- load K,V tiles (tf32-rounded) ----
        {
            const int row = tid >> 1;
            const int cb  = (tid & 1) * 32;
            const float* ksrc = K + base + (size_t)(k0 + row) * DD + cb;
            const float* vsrc = V + base + (size_t)(k0 + row) * DD + cb;
            #pragma unroll
            for (int j = 0; j < 8; ++j) {
                float4 a = *(const float4*)(ksrc + 4 * j);
                *(float4*)&KP[row][cb + 4 * j] =
                    make_float4(tf(a.x), tf(a.y), tf(a.z), tf(a.w));
                float4 v = *(const float4*)(vsrc + 4 * j);
                *(float4*)&Vs[row][cb + 4 * j] =
                    make_float4(tf(v.x), tf(v.y), tf(v.z), tf(v.w));
            }
        }
        __syncthreads();

        // ---- S = (Q/8) K^T : 8 n-atoms (keys) x 8 k-steps (d) ----
        float s[8][4];
        #pragma unroll
        for (int j = 0; j < 8; ++j)
            #pragma unroll
            for (int r = 0; r < 4; ++r) s[j][r] = 0.0f;

        #pragma unroll
        for (int ks = 0; ks < 8; ++ks) {
            #pragma unroll
            for (int na = 0; na < 8; ++na) {
                uint32_t b0 = __float_as_uint(KP[8 * na + g][8 * ks + tig]);
                uint32_t b1 = __float_as_uint(KP[8 * na + g][8 * ks + tig + 4]);
                mma_tf32(s[na], qa[ks][0], qa[ks][1], qa[ks][2], qa[ks][3], b0, b1);
            }
        }

        // ---- causal mask on diagonal tile ----
        if (kv == qt) {
            const int row_lo = m0 + g;
            const int row_hi = m0 + g + 8;
            #pragma unroll
            for (int na = 0; na < 8; ++na) {
                const int col = 8 * na + 2 * tig;
                if (col     > row_lo) s[na][0] = -1e30f;
                if (col + 1 > row_lo) s[na][1] = -1e30f;
                if (col     > row_hi) s[na][2] = -1e30f;
                if (col + 1 > row_hi) s[na][3] = -1e30f;
            }
        }

        // ---- online softmax (rows lo = g, hi = g+8 of this warp's 16) ----
        float tmax_lo = -1e30f, tmax_hi = -1e30f;
        #pragma unroll
        for (int na = 0; na < 8; ++na) {
            tmax_lo = fmaxf(tmax_lo, fmaxf(s[na][0], s[na][1]));
            tmax_hi = fmaxf(tmax_hi, fmaxf(s[na][2], s[na][3]));
        }
        #pragma unroll
        for (int off = 1; off < 4; off <<= 1) {
            tmax_lo = fmaxf(tmax_lo, __shfl_xor_sync(0xffffffffu, tmax_lo, off));
            tmax_hi = fmaxf(tmax_hi, __shfl_xor_sync(0xffffffffu, tmax_hi, off));
        }

        const float mn_lo = fmaxf(m_lo, tmax_lo);
        const float mn_hi = fmaxf(m_hi, tmax_hi);
        const float al_lo = __expf(m_lo - mn_lo);
        const float al_hi = __expf(m_hi - mn_hi);
        m_lo = mn_lo; m_hi = mn_hi;

        float rs_lo = 0.0f, rs_hi = 0.0f;
        #pragma unroll
        for (int na = 0; na < 8; ++na) {
            s[na][0] = __expf(s[na][0] - mn_lo);
            s[na][1] = __expf(s[na][1] - mn_lo);
            s[na][2] = __expf(s[na][2] - mn_hi);
            s[na][3] = __expf(s[na][3] - mn_hi);
            rs_lo += s[na][0] + s[na][1];
            rs_hi += s[na][2] + s[na][3];
        }
        #pragma unroll
        for (int off = 1; off < 4; off <<= 1) {
            rs_lo += __shfl_xor_sync(0xffffffffu, rs_lo, off);
            rs_hi += __shfl_xor_sync(0xffffffffu, rs_hi, off);
        }
        l_lo = l_lo * al_lo + rs_lo;
        l_hi = l_hi * al_hi + rs_hi;

        #pragma unroll
        for (int na = 0; na < 8; ++na) {
            o[na][0] *= al_lo; o[na][1] *= al_lo;
            o[na][2] *= al_hi; o[na][3] *= al_hi;
        }

        __syncthreads();   // all warps done reading Ks

        // ---- write P (tf32-rounded) transposed-for-A into KP: Ps[qrow][key] ----
        #pragma unroll
        for (int na = 0; na < 8; ++na) {
            const int col = 8 * na + 2 * tig;
            *(float2*)&KP[m0 + g][col]     = make_float2(tf(s[na][0]), tf(s[na][1]));
            *(float2*)&KP[m0 + g + 8][col] = make_float2(tf(s[na][2]), tf(s[na][3]));
        }
        __syncthreads();

        // ---- O += P V : 8 k-steps (keys) x 8 n-atoms (d) ----
        #pragma unroll
        for (int ks = 0; ks < 8; ++ks) {
            uint32_t pa0 = __float_as_uint(KP[m0 + g]    [8 * ks + tig]);
            uint32_t pa1 = __float_as_uint(KP[m0 + g + 8][8 * ks + tig]);
            uint32_t pa2 = __float_as_uint(KP[m0 + g]    [8 * ks + tig + 4]);
            uint32_t pa3 = __float_as_uint(KP[m0 + g + 8][8 * ks + tig + 4]);
            #pragma unroll
            for (int na = 0; na < 8; ++na) {
                uint32_t b0 = __float_as_uint(Vs[8 * ks + tig]    [8 * na + g]);
                uint32_t b1 = __float_as_uint(Vs[8 * ks + tig + 4][8 * na + g]);
                mma_tf32(o[na], pa0, pa1, pa2, pa3, b0, b1);
            }
        }
    }

    // ---- finalize ----
    const float inv_lo = 1.0f / l_lo;
    const float inv_hi = 1.0f / l_hi;
    float* out_lo = g_attn + base + (size_t)(q0 + m0 + g) * DD;
    float* out_hi = out_lo + (size_t)8 * DD;
    #pragma unroll
    for (int na = 0; na < 8; ++na) {
        const int col = 8 * na + 2 * tig;
        *(float2*)(out_lo + col) = make_float2(o[na][0] * inv_lo, o[na][1] * inv_lo);
        *(float2*)(out_hi + col) = make_float2(o[na][2] * inv_hi, o[na][3] * inv_hi);
    }
}

// ---------------------------------------------------------------------------
// Projection GEMM with tf32 mma: out[M,N] = A[M,K] @ W[K,N] + b.
// M=4096, N=K=1024.  Block tile 128x128, BK=32, 256 threads (8 warps 4x2),
// warp tile 32x64.
// ---------------------------------------------------------------------------
__global__ __launch_bounds__(256) void proj_tc(
    const float* __restrict__ Wp,
    const float* __restrict__ bp,
    float* __restrict__ out)
{
    __shared__ float As[128][36];   // 18432 B, A[m][k] tf32
    __shared__ float Ws[32][136];   // 17408 B, W[k][n] tf32

    const int tid  = threadIdx.x;
    const int warp = tid >> 5;
    const int lane = tid & 31;
    const int g    = lane >> 2;
    const int tig  = lane & 3;

    const int m0   = blockIdx.y * 128;
    const int n0   = blockIdx.x * 128;
    const int moff = (warp >> 1) * 32;   // 0,32,64,96
    const int noff = (warp & 1) * 64;    // 0,64

    const float* A = g_attn;

    float acc[2][8][4];
    #pragma unroll
    for (int i = 0; i < 2; ++i)
        #pragma unroll
        for (int j = 0; j < 8; ++j)
            #pragma unroll
            for (int r = 0; r < 4; ++r) acc[i][j][r] = 0.0f;

    for (int k0 = 0; k0 < DD; k0 += 32) {
        // ---- stage tiles (tf32-rounded) ----
        #pragma unroll
        for (int i = 0; i < 4; ++i) {
            const int slot = tid + i * 256;           // 0..1023
            const int m = slot >> 3;
            const int k = (slot & 7) * 4;
            float4 a = *(const float4*)(A + (size_t)(m0 + m) * DD + k0 + k);
            *(float4*)&As[m][k] = make_float4(tf(a.x), tf(a.y), tf(a.z), tf(a.w));
        }
        #pragma unroll
        for (int i = 0; i < 4; ++i) {
            const int slot = tid + i * 256;
            const int k = slot >> 5;
            const int n = (slot & 31) * 4;
            float4 w = *(const float4*)(Wp + (size_t)(k0 + k) * DD + n0 + n);
            *(float4*)&Ws[k][n] = make_float4(tf(w.x), tf(w.y), tf(w.z), tf(w.w));
        }
        __syncthreads();

        // ---- 4 k8-steps ----
        #pragma unroll
        for (int s = 0; s < 4; ++s) {
            uint32_t am[2][4];
            #pragma unroll
            for (int i = 0; i < 2; ++i) {
                am[i][0] = __float_as_uint(As[moff + i * 16 + g]    [8 * s + tig]);
                am[i][1] = __float_as_uint(As[moff + i * 16 + 8 + g][8 * s + tig]);
                am[i][2] = __float_as_uint(As[moff + i * 16 + g]    [8 * s + tig + 4]);
                am[i][3] = __float_as_uint(As[moff + i * 16 + 8 + g][8 * s + tig + 4]);
            }
            #pragma unroll
            for (int j = 0; j < 8; ++j) {
                uint32_t b0 = __float_as_uint(Ws[8 * s + tig]    [noff + 8 * j + g]);
                uint32_t b1 = __float_as_uint(Ws[8 * s + tig + 4][noff + 8 * j + g]);
                mma_tf32(acc[0][j], am[0][0], am[0][1], am[0][2], am[0][3], b0, b1);
                mma_tf32(acc[1][j], am[1][0], am[1][1], am[1][2], am[1][3], b0, b1);
            }
        }
        __syncthreads();
    }

    // ---- epilogue: + bias, store ----
    #pragma unroll
    for (int j = 0; j < 8; ++j) {
        const int col = n0 + noff + 8 * j + 2 * tig;
        const float2 bb = *(const float2*)(bp + col);
        #pragma unroll
        for (int i = 0; i < 2; ++i) {
            const int row_lo = m0 + moff + i * 16 + g;
            *(float2*)&out[(size_t)row_lo * DD + col] =
                make_float2(acc[i][j][0] + bb.x, acc[i][j][1] + bb.y);
            *(float2*)&out[(size_t)(row_lo + 8) * DD + col] =
                make_float2(acc[i][j][2] + bb.x, acc[i][j][3] + bb.y);
        }
    }
}

extern "C" void kernel_launch(void* const* d_in, const int* in_sizes, int n_in,
                              void* d_out, int out_size)
{
    const float* Q  = (const float*)d_in[0];
    const float* K  = (const float*)d_in[1];
    const float* V  = (const float*)d_in[2];
    const float* Wp = (const float*)d_in[3];
    const float* bp = (const float*)d_in[4];
    float* out = (float*)d_out;

    dim3 gA(LL / 64, HH, BB);          // (32, 16, 2)
    attn_tc<<<gA, 128>>>(Q, K, V);

    dim3 gP(DD / 128, (BB * LL) / 128); // (8, 32)
    proj_tc<<<gP, 256>>>(Wp, bp, out);
}

// round 15
// speedup vs baseline: 1.0141x; 1.0141x over previous
#include <cuda_runtime.h>
#include <cstdint>

#define BB 2
#define LL 2048
#define DD 1024
#define HH 16
#define DH 64

// scratch for attention output (merged heads), [B, L, D] fp32 = 16 MB
__device__ float g_attn[BB * LL * DD];

// ---------------------------------------------------------------------------
// tf32 helpers
// ---------------------------------------------------------------------------
__device__ __forceinline__ uint32_t f2tf32(float x) {
    uint32_t r;
    asm("cvt.rna.tf32.f32 %0, %1;" : "=r"(r) : "f"(x));
    return r;
}
__device__ __forceinline__ float tf(float x) { return __uint_as_float(f2tf32(x)); }

__device__ __forceinline__ void mma_tf32(float c[4],
                                         uint32_t a0, uint32_t a1, uint32_t a2, uint32_t a3,
                                         uint32_t b0, uint32_t b1)
{
    asm volatile(
        "mma.sync.aligned.m16n8k8.row.col.f32.tf32.tf32.f32 "
        "{%0,%1,%2,%3}, {%4,%5,%6,%7}, {%8,%9}, {%0,%1,%2,%3};\n"
        : "+f"(c[0]), "+f"(c[1]), "+f"(c[2]), "+f"(c[3])
        : "r"(a0), "r"(a1), "r"(a2), "r"(a3), "r"(b0), "r"(b1));
}

// ---------------------------------------------------------------------------
// Flash attention with tf32 tensor-core mma.
// Block: 128 threads = 4 warps; each warp owns 16 query rows (BM=64).
// BN=64 keys per iteration. Q fragments live in registers for the whole loop.
// Smem: KP (K tile as Ks[key][d], reused as Ps[qrow][key]) pad 68,
//       Vs[key][d] pad 72.
// ---------------------------------------------------------------------------
__global__ __launch_bounds__(128) void attn_tc(
    const float* __restrict__ Q,
    const float* __restrict__ K,
    const float* __restrict__ V)
{
    __shared__ float KP[64][68];   // 17408 B
    __shared__ float Vs[64][72];   // 18432 B

    const int tid  = threadIdx.x;
    const int warp = tid >> 5;
    const int lane = tid & 31;
    const int g    = lane >> 2;    // 0..7
    const int tig  = lane & 3;     // 0..3

    const int qt = gridDim.x - 1 - (int)blockIdx.x;   // heavy tiles first
    const int h  = blockIdx.y;
    const int b  = blockIdx.z;
    const int q0 = qt * 64;
    const int m0 = warp * 16;

    const size_t base = (size_t)b * LL * DD + (size_t)h * DH;

    // ---- Q fragments for all 8 k8-chunks of DH=64, pre-scaled by 1/8, tf32 ----
    uint32_t qa[8][4];
    {
        const float* qr0 = Q + base + (size_t)(q0 + m0 + g) * DD;
        const float* qr1 = qr0 + (size_t)8 * DD;
        #pragma unroll
        for (int s = 0; s < 8; ++s) {
            qa[s][0] = f2tf32(qr0[8 * s + tig] * 0.125f);
            qa[s][1] = f2tf32(qr1[8 * s + tig] * 0.125f);
            qa[s][2] = f2tf32(qr0[8 * s + tig + 4] * 0.125f);
            qa[s][3] = f2tf32(qr1[8 * s + tig + 4] * 0.125f);
        }
    }

    float o[8][4];
    #pragma unroll
    for (int j = 0; j < 8; ++j)
        #pragma unroll
        for (int r = 0; r < 4; ++r) o[j][r] = 0.0f;

    float m_lo = -1e30f, m_hi = -1e30f;
    float l_lo = 0.0f,   l_hi = 0.0f;

    for (int kv = 0; kv <= qt; ++kv) {
        const int k0 = kv * 64;

        __syncthreads();   // previous iter done reading KP(Ps) and Vs

        // ---- load K,V tiles (tf32-rounded) ----
        {
            const int row = tid >> 1;
            const int cb  = (tid & 1) * 32;
            const float* ksrc = K + base + (size_t)(k0 + row) * DD + cb;
            const float* vsrc = V + base + (size_t)(k0 + row) * DD + cb;
            #pragma unroll
            for (int j = 0; j < 8; ++j) {
                float4 a = *(const float4*)(ksrc + 4 * j);
                *(float4*)&KP[row][cb + 4 * j] =
                    make_float4(tf(a.x), tf(a.y), tf(a.z), tf(a.w));
                float4 v = *(const float4*)(vsrc + 4 * j);
                *(float4*)&Vs[row][cb + 4 * j] =
                    make_float4(tf(v.x), tf(v.y), tf(v.z), tf(v.w));
            }
        }
        __syncthreads();

        // ---- S = (Q/8) K^T : 8 n-atoms (keys) x 8 k-steps (d) ----
        float s[8][4];
        #pragma unroll
        for (int j = 0; j < 8; ++j)
            #pragma unroll
            for (int r = 0; r < 4; ++r) s[j][r] = 0.0f;

        #pragma unroll
        for (int ks = 0; ks < 8; ++ks) {
            #pragma unroll
            for (int na = 0; na < 8; ++na) {
                uint32_t b0 = __float_as_uint(KP[8 * na + g][8 * ks + tig]);
                uint32_t b1 = __float_as_uint(KP[8 * na + g][8 * ks + tig + 4]);
                mma_tf32(s[na], qa[ks][0], qa[ks][1], qa[ks][2], qa[ks][3], b0, b1);
            }
        }

        // ---- causal mask on diagonal tile ----
        if (kv == qt) {
            const int row_lo = m0 + g;
            const int row_hi = m0 + g + 8;
            #pragma unroll
            for (int na = 0; na < 8; ++na) {
                const int col = 8 * na + 2 * tig;
                if (col     > row_lo) s[na][0] = -1e30f;
                if (col + 1 > row_lo) s[na][1] = -1e30f;
                if (col     > row_hi) s[na][2] = -1e30f;
                if (col + 1 > row_hi) s[na][3] = -1e30f;
            }
        }

        // ---- online softmax (rows lo = g, hi = g+8 of this warp's 16) ----
        float tmax_lo = -1e30f, tmax_hi = -1e30f;
        #pragma unroll
        for (int na = 0; na < 8; ++na) {
            tmax_lo = fmaxf(tmax_lo, fmaxf(s[na][0], s[na][1]));
            tmax_hi = fmaxf(tmax_hi, fmaxf(s[na][2], s[na][3]));
        }
        #pragma unroll
        for (int off = 1; off < 4; off <<= 1) {
            tmax_lo = fmaxf(tmax_lo, __shfl_xor_sync(0xffffffffu, tmax_lo, off));
            tmax_hi = fmaxf(tmax_hi, __shfl_xor_sync(0xffffffffu, tmax_hi, off));
        }

        const float mn_lo = fmaxf(m_lo, tmax_lo);
        const float mn_hi = fmaxf(m_hi, tmax_hi);
        const float al_lo = __expf(m_lo - mn_lo);
        const float al_hi = __expf(m_hi - mn_hi);
        m_lo = mn_lo; m_hi = mn_hi;

        float rs_lo = 0.0f, rs_hi = 0.0f;
        #pragma unroll
        for (int na = 0; na < 8; ++na) {
            s[na][0] = __expf(s[na][0] - mn_lo);
            s[na][1] = __expf(s[na][1] - mn_lo);
            s[na][2] = __expf(s[na][2] - mn_hi);
            s[na][3] = __expf(s[na][3] - mn_hi);
            rs_lo += s[na][0] + s[na][1];
            rs_hi += s[na][2] + s[na][3];
        }
        #pragma unroll
        for (int off = 1; off < 4; off <<= 1) {
            rs_lo += __shfl_xor_sync(0xffffffffu, rs_lo, off);
            rs_hi += __shfl_xor_sync(0xffffffffu, rs_hi, off);
        }
        l_lo = l_lo * al_lo + rs_lo;
        l_hi = l_hi * al_hi + rs_hi;

        #pragma unroll
        for (int na = 0; na < 8; ++na) {
            o[na][0] *= al_lo; o[na][1] *= al_lo;
            o[na][2] *= al_hi; o[na][3] *= al_hi;
        }

        __syncthreads();   // all warps done reading Ks

        // ---- write P (tf32-rounded) transposed-for-A into KP: Ps[qrow][key] ----
        #pragma unroll
        for (int na = 0; na < 8; ++na) {
            const int col = 8 * na + 2 * tig;
            *(float2*)&KP[m0 + g][col]     = make_float2(tf(s[na][0]), tf(s[na][1]));
            *(float2*)&KP[m0 + g + 8][col] = make_float2(tf(s[na][2]), tf(s[na][3]));
        }
        __syncthreads();

        // ---- O += P V : 8 k-steps (keys) x 8 n-atoms (d) ----
        #pragma unroll
        for (int ks = 0; ks < 8; ++ks) {
            uint32_t pa0 = __float_as_uint(KP[m0 + g]    [8 * ks + tig]);
            uint32_t pa1 = __float_as_uint(KP[m0 + g + 8][8 * ks + tig]);
            uint32_t pa2 = __float_as_uint(KP[m0 + g]    [8 * ks + tig + 4]);
            uint32_t pa3 = __float_as_uint(KP[m0 + g + 8][8 * ks + tig + 4]);
            #pragma unroll
            for (int na = 0; na < 8; ++na) {
                uint32_t b0 = __float_as_uint(Vs[8 * ks + tig]    [8 * na + g]);
                uint32_t b1 = __float_as_uint(Vs[8 * ks + tig + 4][8 * na + g]);
                mma_tf32(o[na], pa0, pa1, pa2, pa3, b0, b1);
            }
        }
    }

    // ---- finalize ----
    const float inv_lo = 1.0f / l_lo;
    const float inv_hi = 1.0f / l_hi;
    float* out_lo = g_attn + base + (size_t)(q0 + m0 + g) * DD;
    float* out_hi = out_lo + (size_t)8 * DD;
    #pragma unroll
    for (int na = 0; na < 8; ++na) {
        const int col = 8 * na + 2 * tig;
        *(float2*)(out_lo + col) = make_float2(o[na][0] * inv_lo, o[na][1] * inv_lo);
        *(float2*)(out_hi + col) = make_float2(o[na][2] * inv_hi, o[na][3] * inv_hi);
    }
}

// ---------------------------------------------------------------------------
// Projection GEMM with tf32 mma: out[M,N] = A[M,K] @ W[K,N] + b.
// M=4096, N=K=1024.  Block tile 128x128, BK=32, 256 threads (8 warps 4x2),
// warp tile 32x64.
// ---------------------------------------------------------------------------
__global__ __launch_bounds__(256) void proj_tc(
    const float* __restrict__ Wp,
    const float* __restrict__ bp,
    float* __restrict__ out)
{
    __shared__ float As[128][36];   // 18432 B, A[m][k] tf32
    __shared__ float Ws[32][136];   // 17408 B, W[k][n] tf32

    const int tid  = threadIdx.x;
    const int warp = tid >> 5;
    const int lane = tid & 31;
    const int g    = lane >> 2;
    const int tig  = lane & 3;

    const int m0   = blockIdx.y * 128;
    const int n0   = blockIdx.x * 128;
    const int moff = (warp >> 1) * 32;   // 0,32,64,96
    const int noff = (warp & 1) * 64;    // 0,64

    const float* A = g_attn;

    float acc[2][8][4];
    #pragma unroll
    for (int i = 0; i < 2; ++i)
        #pragma unroll
        for (int j = 0; j < 8; ++j)
            #pragma unroll
            for (int r = 0; r < 4; ++r) acc[i][j][r] = 0.0f;

    for (int k0 = 0; k0 < DD; k0 += 32) {
        // ---- stage tiles (tf32-rounded) ----
        #pragma unroll
        for (int i = 0; i < 4; ++i) {
            const int slot = tid + i * 256;           // 0..1023
            const int m = slot >> 3;
            const int k = (slot & 7) * 4;
            float4 a = *(const float4*)(A + (size_t)(m0 + m) * DD + k0 + k);
            *(float4*)&As[m][k] = make_float4(tf(a.x), tf(a.y), tf(a.z), tf(a.w));
        }
        #pragma unroll
        for (int i = 0; i < 4; ++i) {
            const int slot = tid + i * 256;
            const int k = slot >> 5;
            const int n = (slot & 31) * 4;
            float4 w = *(const float4*)(Wp + (size_t)(k0 + k) * DD + n0 + n);
            *(float4*)&Ws[k][n] = make_float4(tf(w.x), tf(w.y), tf(w.z), tf(w.w));
        }
        __syncthreads();

        // ---- 4 k8-steps ----
        #pragma unroll
        for (int s = 0; s < 4; ++s) {
            uint32_t am[2][4];
            #pragma unroll
            for (int i = 0; i < 2; ++i) {
                am[i][0] = __float_as_uint(As[moff + i * 16 + g]    [8 * s + tig]);
                am[i][1] = __float_as_uint(As[moff + i * 16 + 8 + g][8 * s + tig]);
                am[i][2] = __float_as_uint(As[moff + i * 16 + g]    [8 * s + tig + 4]);
                am[i][3] = __float_as_uint(As[moff + i * 16 + 8 + g][8 * s + tig + 4]);
            }
            #pragma unroll
            for (int j = 0; j < 8; ++j) {
                uint32_t b0 = __float_as_uint(Ws[8 * s + tig]    [noff + 8 * j + g]);
                uint32_t b1 = __float_as_uint(Ws[8 * s + tig + 4][noff + 8 * j + g]);
                mma_tf32(acc[0][j], am[0][0], am[0][1], am[0][2], am[0][3], b0, b1);
                mma_tf32(acc[1][j], am[1][0], am[1][1], am[1][2], am[1][3], b0, b1);
            }
        }
        __syncthreads();
    }

    // ---- epilogue: + bias, store ----
    #pragma unroll
    for (int j = 0; j < 8; ++j) {
        const int col = n0 + noff + 8 * j + 2 * tig;
        const float2 bb = *(const float2*)(bp + col);
        #pragma unroll
        for (int i = 0; i < 2; ++i) {
            const int row_lo = m0 + moff + i * 16 + g;
            *(float2*)&out[(size_t)row_lo * DD + col] =
                make_float2(acc[i][j][0] + bb.x, acc[i][j][1] + bb.y);
            *(float2*)&out[(size_t)(row_lo + 8) * DD + col] =
                make_float2(acc[i][j][2] + bb.x, acc[i][j][3] + bb.y);
        }
    }
}

extern "C" void kernel_launch(void* const* d_in, const int* in_sizes, int n_in,
                              void* d_out, int out_size)
{
    const float* Q  = (const float*)d_in[0];
    const float* K  = (const float*)d_in[1];
    const float* V  = (const float*)d_in[2];
    const float* Wp = (const float*)d_in[3];
    const float* bp = (const float*)d_in[4];
    float* out = (float*)d_out;

    dim3 gA(LL / 64, HH, BB);          // (32, 16, 2)
    attn_tc<<<gA, 128>>>(Q, K, V);

    dim3 gP(DD / 128, (BB * LL) / 128); // (8, 32)
    proj_tc<<<gP, 256>>>(Wp, bp, out);
}